// round 10
// baseline (speedup 1.0000x reference)
#include <cuda_runtime.h>
#include <cuda_fp16.h>
#include <mma.h>
#include <math.h>
#include <stdint.h>

using namespace nvcuda;

// Linear attention, wmma m16n16k16 + 3xFP16 hi/lo splitting.
// R9b: every tensor split to fp16 hi/lo exactly ONCE (elementwise converts or
// GEMM epilogues); all GEMM mainloop fills are pure fp16 copies.
// No global transposes (smem-level trans fills only — proven R7/R8).
//   conv:  xh/xl = split(x);  wh/wl = split(256*W)
//   proj:  acc = x @ 256W;  qh/ql = split(exp(acc/256)/16) = split(16*q'')
//   zc  :  zc[l] = 4096 / (16*sum(qh+ql) + 1e-8)
//   kv  :  acc = (16k'')^T @ x = kv/16;  kvh/kvl = split(acc/16) = split(kv/256)
//   num :  acc = (16q'') @ (kv/256) = q'*kv/4096;  out = acc * zc[l]

#define BATCH 8
#define LSEQ  4096
#define DDIM  1024
#define EDIM  256
#define BL    (BATCH * LSEQ)
#define SP    136            // padded smem row pitch (halves)
#define TILE  (16 * SP)

// ---- scratch ----
__device__ __align__(16) __half g_xh[(size_t)BL * DDIM];   // [l][d]
__device__ __align__(16) __half g_xl[(size_t)BL * DDIM];
__device__ __align__(16) __half g_wqh[DDIM * EDIM];        // [d][e], 256W
__device__ __align__(16) __half g_wql[DDIM * EDIM];
__device__ __align__(16) __half g_wkh[DDIM * EDIM];
__device__ __align__(16) __half g_wkl[DDIM * EDIM];
__device__ __align__(16) __half g_qh[(size_t)BL * EDIM];   // [l][e], 16q''
__device__ __align__(16) __half g_ql[(size_t)BL * EDIM];
__device__ __align__(16) __half g_kh[(size_t)BL * EDIM];
__device__ __align__(16) __half g_kl[(size_t)BL * EDIM];
__device__ __align__(16) __half g_kvh[(size_t)BATCH * EDIM * DDIM];  // [b][e][d]
__device__ __align__(16) __half g_kvl[(size_t)BATCH * EDIM * DDIM];
__device__ float g_zc[BL];

// ---------------- helpers ----------------
__device__ __forceinline__ void split2(float x, __half& h, __half& l) {
    h = __float2half_rn(x);
    l = __float2half_rn(x - __half2float(h));
}
__device__ __forceinline__ void mma_step(
    const __half* Ah, const __half* Al, const __half* Bh, const __half* Bl,
    wmma::fragment<wmma::accumulator, 16, 16, 16, float> acc[4][2],
    int warpM, int warpN)
{
    wmma::fragment<wmma::matrix_a, 16, 16, 16, __half, wmma::col_major> ah[4], al[4];
    wmma::fragment<wmma::matrix_b, 16, 16, 16, __half, wmma::row_major> bh[2], bl[2];
#pragma unroll
    for (int mi = 0; mi < 4; mi++) {
        int m0 = warpM * 64 + mi * 16;
        wmma::load_matrix_sync(ah[mi], Ah + m0, SP);
        wmma::load_matrix_sync(al[mi], Al + m0, SP);
    }
#pragma unroll
    for (int nj = 0; nj < 2; nj++) {
        int n0 = warpN * 32 + nj * 16;
        wmma::load_matrix_sync(bh[nj], Bh + n0, SP);
        wmma::load_matrix_sync(bl[nj], Bl + n0, SP);
    }
#pragma unroll
    for (int mi = 0; mi < 4; mi++)
#pragma unroll
        for (int nj = 0; nj < 2; nj++) {
            wmma::mma_sync(acc[mi][nj], ah[mi], bh[nj], acc[mi][nj]);
            wmma::mma_sync(acc[mi][nj], ah[mi], bl[nj], acc[mi][nj]);
            wmma::mma_sync(acc[mi][nj], al[mi], bh[nj], acc[mi][nj]);
        }
}

// direct copy fill: src [k][n] fp16 (hi,lo), stride s; tile [16][128].
__device__ __forceinline__ void ld_dir(uint4 v[2], const __half* __restrict__ sh,
                                       const __half* __restrict__ sl,
                                       size_t stride, int tid) {
    int k = tid >> 4, n8 = (tid & 15) * 8;
    v[0] = *(const uint4*)(sh + (size_t)k * stride + n8);
    v[1] = *(const uint4*)(sl + (size_t)k * stride + n8);
}
__device__ __forceinline__ void st_dir(__half* dh, __half* dl, const uint4 v[2], int tid) {
    int k = tid >> 4, n8 = (tid & 15) * 8;
    *(uint4*)(dh + k * SP + n8) = v[0];
    *(uint4*)(dl + k * SP + n8) = v[1];
}
// transposed copy fill: src [m][k] fp16 (hi,lo), stride s; tile [16 k][128 m].
__device__ __forceinline__ void ld_tr(uint4 v[2], const __half* __restrict__ sh,
                                      const __half* __restrict__ sl,
                                      size_t stride, int tid) {
    int m = tid >> 1, k0 = (tid & 1) * 8;
    v[0] = *(const uint4*)(sh + (size_t)m * stride + k0);
    v[1] = *(const uint4*)(sl + (size_t)m * stride + k0);
}
__device__ __forceinline__ void st_tr(__half* dh, __half* dl, const uint4 v[2], int tid) {
    int m = tid >> 1, k0 = (tid & 1) * 8;
    const __half* hh = (const __half*)&v[0];
    const __half* hl = (const __half*)&v[1];
#pragma unroll
    for (int j = 0; j < 8; j++) {
        dh[(k0 + j) * SP + m] = hh[j];
        dl[(k0 + j) * SP + m] = hl[j];
    }
}

#define DECL_SMEM __shared__ __align__(32) __half S[2][4][TILE]
#define ACC_DECL                                                               \
    wmma::fragment<wmma::accumulator, 16, 16, 16, float> acc[4][2];            \
    _Pragma("unroll") for (int mi = 0; mi < 4; mi++)                           \
    _Pragma("unroll") for (int nj = 0; nj < 2; nj++)                           \
        wmma::fill_fragment(acc[mi][nj], 0.0f)

// ---------------- convert kernels ----------------
__global__ __launch_bounds__(256) void conv_x(const float4* __restrict__ x) {
    size_t i = (size_t)blockIdx.x * 256 + threadIdx.x;   // BL*DDIM/4
    float4 v = x[i];
    __half h[4], l[4];
    split2(v.x, h[0], l[0]); split2(v.y, h[1], l[1]);
    split2(v.z, h[2], l[2]); split2(v.w, h[3], l[3]);
    ((uint2*)g_xh)[i] = *(uint2*)h;
    ((uint2*)g_xl)[i] = *(uint2*)l;
}
__global__ __launch_bounds__(256) void conv_w(const float4* __restrict__ qw,
                                              const float4* __restrict__ kw) {
    size_t i = (size_t)blockIdx.x * 256 + threadIdx.x;   // DDIM*EDIM/4
    const float4* W = blockIdx.y ? kw : qw;
    __half* oh = blockIdx.y ? g_wkh : g_wqh;
    __half* ol = blockIdx.y ? g_wkl : g_wql;
    float4 v = W[i];
    __half h[4], l[4];
    split2(v.x * 256.0f, h[0], l[0]); split2(v.y * 256.0f, h[1], l[1]);
    split2(v.z * 256.0f, h[2], l[2]); split2(v.w * 256.0f, h[3], l[3]);
    ((uint2*)oh)[i] = *(uint2*)h;
    ((uint2*)ol)[i] = *(uint2*)l;
}

// ---------------- proj: grid (2, BL/128, 2) ----------------
__global__ __launch_bounds__(256, 1) void proj_kernel()
{
    DECL_SMEM;
    const int tid = threadIdx.x, lane = tid & 31, wid = tid >> 5;
    const int warpM = wid >> 2, warpN = wid & 3;
    const int mBase = blockIdx.y * 128, nBase = blockIdx.x * 128;
    const __half* Ah = g_xh + (size_t)mBase * DDIM;     // [m][k] trans
    const __half* Al = g_xl + (size_t)mBase * DDIM;
    const __half* Bh = (blockIdx.z ? g_wkh : g_wqh) + nBase;  // [k][n] direct
    const __half* Bl = (blockIdx.z ? g_wkl : g_wql) + nBase;
    __half* Oh = blockIdx.z ? g_kh : g_qh;
    __half* Ol = blockIdx.z ? g_kl : g_ql;

    ACC_DECL;
    const int NK = DDIM / 16;
    uint4 vA[2], vB[2];
    ld_tr(vA, Ah, Al, DDIM, tid);
    ld_dir(vB, Bh, Bl, EDIM, tid);
    st_tr(S[0][0], S[0][1], vA, tid);
    st_dir(S[0][2], S[0][3], vB, tid);
    __syncthreads();
    for (int t = 0; t < NK; t++) {
        if (t + 1 < NK) {
            int ko = (t + 1) * 16;
            ld_tr(vA, Ah + ko, Al + ko, DDIM, tid);
            size_t bo = (size_t)ko * EDIM;
            ld_dir(vB, Bh + bo, Bl + bo, EDIM, tid);
        }
        int s = t & 1;
        mma_step(S[s][0], S[s][1], S[s][2], S[s][3], acc, warpM, warpN);
        if (t + 1 < NK) {
            int s2 = (t + 1) & 1;
            st_tr(S[s2][0], S[s2][1], vA, tid);
            st_dir(S[s2][2], S[s2][3], vB, tid);
        }
        __syncthreads();
    }

    // epilogue: v = exp(acc/256)/16 (= 16*q''), split hi/lo, coalesced write
    float* stage = reinterpret_cast<float*>(&S[0][0][0]) + wid * 256;
    const float ie = 1.0f / 256.0f;
    const int r = lane >> 1, c0 = (lane & 1) * 8;
#pragma unroll
    for (int mi = 0; mi < 4; mi++)
#pragma unroll
        for (int nj = 0; nj < 2; nj++) {
            wmma::store_matrix_sync(stage, acc[mi][nj], 16, wmma::mem_row_major);
            __syncwarp();
            int rg = mBase + warpM * 64 + mi * 16 + r;
            int cg = nBase + warpN * 32 + nj * 16 + c0;
            __half hb[8], lb[8];
#pragma unroll
            for (int j = 0; j < 8; j++) {
                float v = expf(stage[r * 16 + c0 + j] * ie) * 0.0625f;
                split2(v, hb[j], lb[j]);
            }
            *(uint4*)(Oh + (size_t)rg * EDIM + cg) = *(uint4*)hb;
            *(uint4*)(Ol + (size_t)rg * EDIM + cg) = *(uint4*)lb;
            __syncwarp();
        }
}

// ---------------- zc: one warp per row ----------------
__global__ __launch_bounds__(256) void zc_kernel()
{
    int row = (int)((blockIdx.x * 256 + threadIdx.x) >> 5);
    int lane = threadIdx.x & 31;
    const __half2* ph = (const __half2*)(g_qh + (size_t)row * EDIM);
    const __half2* pl = (const __half2*)(g_ql + (size_t)row * EDIM);
    float s = 0.0f;
#pragma unroll
    for (int i = 0; i < 4; i++) {
        float2 h = __half22float2(ph[lane + 32 * i]);
        float2 l = __half22float2(pl[lane + 32 * i]);
        s += (h.x + h.y) + (l.x + l.y);
    }
#pragma unroll
    for (int o = 16; o; o >>= 1) s += __shfl_xor_sync(0xffffffffu, s, o);
    if (lane == 0) g_zc[row] = 4096.0f / (16.0f * s + 1e-8f);
}

// ---------------- kv: grid (8, 2, 8).  acc = (16k'')^T @ x = kv/16 ----------
__global__ __launch_bounds__(256, 1) void kv_kernel()
{
    DECL_SMEM;
    const int tid = threadIdx.x, lane = tid & 31, wid = tid >> 5;
    const int warpM = wid >> 2, warpN = wid & 3;
    const int b = blockIdx.z;
    const int mBase = blockIdx.y * 128;   // e
    const int nBase = blockIdx.x * 128;   // d
    const __half* Ah = g_kh + (size_t)b * LSEQ * EDIM + mBase;  // [l][e] direct
    const __half* Al = g_kl + (size_t)b * LSEQ * EDIM + mBase;
    const __half* Bh = g_xh + (size_t)b * LSEQ * DDIM + nBase;  // [l][d] direct
    const __half* Bl = g_xl + (size_t)b * LSEQ * DDIM + nBase;

    ACC_DECL;
    const int NK = LSEQ / 16;
    uint4 vA[2], vB[2];
    ld_dir(vA, Ah, Al, EDIM, tid);
    ld_dir(vB, Bh, Bl, DDIM, tid);
    st_dir(S[0][0], S[0][1], vA, tid);
    st_dir(S[0][2], S[0][3], vB, tid);
    __syncthreads();
    for (int t = 0; t < NK; t++) {
        if (t + 1 < NK) {
            size_t ao = (size_t)(t + 1) * 16 * EDIM;
            size_t bo = (size_t)(t + 1) * 16 * DDIM;
            ld_dir(vA, Ah + ao, Al + ao, EDIM, tid);
            ld_dir(vB, Bh + bo, Bl + bo, DDIM, tid);
        }
        int s = t & 1;
        mma_step(S[s][0], S[s][1], S[s][2], S[s][3], acc, warpM, warpN);
        if (t + 1 < NK) {
            int s2 = (t + 1) & 1;
            st_dir(S[s2][0], S[s2][1], vA, tid);
            st_dir(S[s2][2], S[s2][3], vB, tid);
        }
        __syncthreads();
    }

    // epilogue: kvh/kvl = split(acc/16) = split(kv/256)
    float* stage = reinterpret_cast<float*>(&S[0][0][0]) + wid * 256;
    __half* Oh = g_kvh + (size_t)b * EDIM * DDIM;
    __half* Ol = g_kvl + (size_t)b * EDIM * DDIM;
    const int r = lane >> 1, c0 = (lane & 1) * 8;
#pragma unroll
    for (int mi = 0; mi < 4; mi++)
#pragma unroll
        for (int nj = 0; nj < 2; nj++) {
            wmma::store_matrix_sync(stage, acc[mi][nj], 16, wmma::mem_row_major);
            __syncwarp();
            int rg = mBase + warpM * 64 + mi * 16 + r;
            int cg = nBase + warpN * 32 + nj * 16 + c0;
            __half hb[8], lb[8];
#pragma unroll
            for (int j = 0; j < 8; j++)
                split2(stage[r * 16 + c0 + j] * 0.0625f, hb[j], lb[j]);
            *(uint4*)(Oh + (size_t)rg * DDIM + cg) = *(uint4*)hb;
            *(uint4*)(Ol + (size_t)rg * DDIM + cg) = *(uint4*)lb;
            __syncwarp();
        }
}

// ---------------- num: grid (8, 32, 8).  out = acc * zc[l] ----------------
__global__ __launch_bounds__(256, 1) void num_kernel(float* __restrict__ out)
{
    DECL_SMEM;
    const int tid = threadIdx.x, lane = tid & 31, wid = tid >> 5;
    const int warpM = wid >> 2, warpN = wid & 3;
    const int b = blockIdx.z;
    const int mBase = blockIdx.y * 128;   // l
    const int nBase = blockIdx.x * 128;   // d
    const __half* Ah = g_qh + ((size_t)b * LSEQ + mBase) * EDIM;  // [l][e] trans
    const __half* Al = g_ql + ((size_t)b * LSEQ + mBase) * EDIM;
    const __half* Bh = g_kvh + (size_t)b * EDIM * DDIM + nBase;   // [e][d] direct
    const __half* Bl = g_kvl + (size_t)b * EDIM * DDIM + nBase;

    ACC_DECL;
    const int NK = EDIM / 16;
    uint4 vA[2], vB[2];
    ld_tr(vA, Ah, Al, EDIM, tid);
    ld_dir(vB, Bh, Bl, DDIM, tid);
    st_tr(S[0][0], S[0][1], vA, tid);
    st_dir(S[0][2], S[0][3], vB, tid);
    __syncthreads();
    for (int t = 0; t < NK; t++) {
        if (t + 1 < NK) {
            int ko = (t + 1) * 16;
            ld_tr(vA, Ah + ko, Al + ko, EDIM, tid);
            size_t bo = (size_t)ko * DDIM;
            ld_dir(vB, Bh + bo, Bl + bo, DDIM, tid);
        }
        int s = t & 1;
        mma_step(S[s][0], S[s][1], S[s][2], S[s][3], acc, warpM, warpN);
        if (t + 1 < NK) {
            int s2 = (t + 1) & 1;
            st_tr(S[s2][0], S[s2][1], vA, tid);
            st_dir(S[s2][2], S[s2][3], vB, tid);
        }
        __syncthreads();
    }

    // epilogue: out = acc * zc[row]
    float* stage = reinterpret_cast<float*>(&S[0][0][0]) + wid * 256;
    float* O = out + (size_t)b * LSEQ * DDIM;
    const int r = lane >> 1, c0 = (lane & 1) * 8;
#pragma unroll
    for (int mi = 0; mi < 4; mi++)
#pragma unroll
        for (int nj = 0; nj < 2; nj++) {
            wmma::store_matrix_sync(stage, acc[mi][nj], 16, wmma::mem_row_major);
            __syncwarp();
            int rg = mBase + warpM * 64 + mi * 16 + r;
            int cg = nBase + warpN * 32 + nj * 16 + c0;
            float zc = g_zc[b * LSEQ + rg];
            float ob[8];
#pragma unroll
            for (int j = 0; j < 8; j++)
                ob[j] = stage[r * 16 + c0 + j] * zc;
            *(float4*)(O + (size_t)rg * DDIM + cg)     = *(float4*)&ob[0];
            *(float4*)(O + (size_t)rg * DDIM + cg + 4) = *(float4*)&ob[4];
            __syncwarp();
        }
}

// ---------------- launch ----------------
extern "C" void kernel_launch(void* const* d_in, const int* in_sizes, int n_in,
                              void* d_out, int out_size)
{
    const float* x  = (const float*)d_in[0];
    const float* qw = (const float*)d_in[1];
    const float* kw = (const float*)d_in[2];
    float* out = (float*)d_out;

    conv_x<<<(int)((size_t)BL * DDIM / 4 / 256), 256>>>((const float4*)x);
    conv_w<<<dim3(DDIM * EDIM / 4 / 256, 2), 256>>>((const float4*)qw,
                                                    (const float4*)kw);
    proj_kernel<<<dim3(EDIM / 128, BL / 128, 2), 256>>>();
    zc_kernel<<<BL / 8, 256>>>();
    kv_kernel<<<dim3(DDIM / 128, EDIM / 128, BATCH), 256>>>();
    num_kernel<<<dim3(DDIM / 128, LSEQ / 128, BATCH), 256>>>(out);
}